// round 15
// baseline (speedup 1.0000x reference)
#include <cuda_runtime.h>
#include <cuda_fp16.h>
#include <math.h>
#include <stdint.h>

#define BB 8
#define TT 2048
#define EE 128
#define HH 256
#define BT (BB*TT)

#define QP  264    // halves pitch for Q/K/V smem tiles (row step = +4 banks)
#define XP  136    // halves pitch for proj tiles

// fp16 scratch
__device__ __half g_Xh[(size_t)BT*EE];     // x converted to fp16
__device__ __half g_Wh[3*EE*HH];           // W (Q-scale folded), fp16
__device__ __half g_bh[3*HH];              // biases (Q-scale folded), fp16
__device__ __half g_Qh[(size_t)BT*HH];
__device__ __half g_Kh[(size_t)BT*HH];
__device__ __half g_Vh[(size_t)BT*HH];

// split-KV partials (no-max softmax -> only O and l needed)
__device__ float g_Op[2][64][128*256];
__device__ float g_lp[2][64][128];

// LPT schedule: kind 0=light full, 1=heavy half0 (0..qt), 2=heavy half1 (qt+1..2qt+1)
__constant__ int c_qt[24]   = {15,15,7,14,14,6,13,13,12,12,5,11,11,10,10,4,9,9,8,8,3,2,1,0};
__constant__ int c_kind[24] = { 1, 2,0, 1, 2,0, 1, 2, 1, 2,0, 1, 2, 1, 2,0,1,2,1,2,0,0,0,0};

__device__ __forceinline__ unsigned su32(const void* p) {
    return (unsigned)__cvta_generic_to_shared(p);
}
__device__ __forceinline__ void ldsm_x4(unsigned* r, unsigned a) {
    asm volatile("ldmatrix.sync.aligned.m8n8.x4.shared.b16 {%0,%1,%2,%3}, [%4];"
        : "=r"(r[0]), "=r"(r[1]), "=r"(r[2]), "=r"(r[3]) : "r"(a));
}
__device__ __forceinline__ void ldsm_x4t(unsigned* r, unsigned a) {
    asm volatile("ldmatrix.sync.aligned.m8n8.x4.trans.shared.b16 {%0,%1,%2,%3}, [%4];"
        : "=r"(r[0]), "=r"(r[1]), "=r"(r[2]), "=r"(r[3]) : "r"(a));
}
__device__ __forceinline__ void mma16(float* d, const unsigned* a, unsigned b0, unsigned b1) {
    asm volatile("mma.sync.aligned.m16n8k16.row.col.f32.f16.f16.f32 "
        "{%0,%1,%2,%3},{%4,%5,%6,%7},{%8,%9},{%0,%1,%2,%3};"
        : "+f"(d[0]), "+f"(d[1]), "+f"(d[2]), "+f"(d[3])
        : "r"(a[0]), "r"(a[1]), "r"(a[2]), "r"(a[3]), "r"(b0), "r"(b1));
}
__device__ __forceinline__ void cpa16(unsigned d, const void* s) {
    asm volatile("cp.async.cg.shared.global [%0], [%1], 16;" :: "r"(d), "l"(s));
}
#define CP_COMMIT() asm volatile("cp.async.commit_group;")
#define CP_WAIT0()  asm volatile("cp.async.wait_group 0;")
#define CP_WAIT1()  asm volatile("cp.async.wait_group 1;")

#define MBARRIER_INIT(mbar, count) \
    asm volatile("mbarrier.init.shared.b64 [%0], %1;" \
        :: "r"((uint32_t)(mbar)), "r"((uint32_t)(count)) : "memory")
#define MBARRIER_ARRIVE(mbar) \
    asm volatile("mbarrier.arrive.shared.b64 _, [%0];" \
        :: "r"((uint32_t)(mbar)) : "memory")
#define MBARRIER_WAIT_PARITY(mbar, parity) do { \
    uint32_t _m = (uint32_t)(mbar); uint32_t _p = (uint32_t)(parity); uint32_t _d; \
    asm volatile("{\n\t.reg .pred p;\n\t" \
        "mbarrier.try_wait.parity.acquire.cta.shared::cta.b64 p, [%1], %2;\n\t" \
        "selp.b32 %0, 1, 0, p;\n\t}" : "=r"(_d) : "r"(_m), "r"(_p) : "memory"); \
    if (!_d) { \
        asm volatile("{\n\t.reg .pred P1;\n\t" \
            "WL_%=:\n\t" \
            "mbarrier.try_wait.parity.acquire.cta.shared::cta.b64 P1, [%0], %1, 0x989680;\n\t" \
            "@P1 bra.uni WD_%=;\n\t" \
            "bra.uni WL_%=;\n\t" \
            "WD_%=:\n\t}" :: "r"(_m), "r"(_p) : "memory"); \
    } } while (0)

__device__ __forceinline__ float ex2(float x) {
    float y; asm("ex2.approx.ftz.f32 %0, %1;" : "=f"(y) : "f"(x)); return y;
}
__device__ __forceinline__ unsigned h2u(float a, float b) {
    __half2 h = __floats2half2_rn(a, b);
    return *reinterpret_cast<unsigned*>(&h);
}

// S(16x64) = Q(16x256) K(64x256)^T for one warp. aQ/aK are per-warp ldsm bases.
__device__ __forceinline__ void compute_S(float S[8][4], unsigned aQ, unsigned aK) {
    #pragma unroll
    for (int nf = 0; nf < 8; nf++)
        #pragma unroll
        for (int c = 0; c < 4; c++) S[nf][c] = 0.0f;
    #pragma unroll
    for (int kb = 0; kb < 16; kb++) {
        unsigned qf[4];
        ldsm_x4(qf, aQ + kb * 32);
        #pragma unroll
        for (int j = 0; j < 4; j++) {
            unsigned bf[4];
            ldsm_x4(bf, aK + (j * 16 * QP + kb * 16) * 2);
            mma16(S[2 * j],     qf, bf[0], bf[2]);
            mma16(S[2 * j + 1], qf, bf[1], bf[3]);
        }
    }
}

// ---------------------------------------------------------------------------
// prep: fp32 -> fp16 conversions. Folds the softmax scale (log2e/16) into
// Wq and bq so Q comes out pre-scaled.
// grid = 1024 (x: 1024*256*2 = 524288 float4 exactly) + 48 (W) + 1 (bias).
// ---------------------------------------------------------------------------
#define QSCALE 0.0901679843431555f

__global__ __launch_bounds__(256, 4) void prep_kernel(
    const float* __restrict__ x,
    const float* __restrict__ Wq, const float* __restrict__ bq,
    const float* __restrict__ Wk, const float* __restrict__ bk,
    const float* __restrict__ Wv, const float* __restrict__ bv)
{
    const int bx = blockIdx.x;
    const int tid = threadIdx.x;
    if (bx < 1024) {
        // x: 2,097,152 floats = 524,288 float4; 1024 blocks x 256 thr x 2
        const float4* xs = reinterpret_cast<const float4*>(x);
        #pragma unroll
        for (int k = 0; k < 2; k++) {
            size_t f = (size_t)bx * 256 + tid + (size_t)k * 262144;
            float4 v = xs[f];
            reinterpret_cast<__half2*>(g_Xh)[2 * f]     = __floats2half2_rn(v.x, v.y);
            reinterpret_cast<__half2*>(g_Xh)[2 * f + 1] = __floats2half2_rn(v.z, v.w);
        }
    } else if (bx < 1024 + 48) {
        const int wb = bx - 1024;
        const int z = wb >> 4;                 // 0..2
        const int off = (wb & 15) * 2048;      // element offset within W (32768)
        const float* W = (z == 0) ? Wq : ((z == 1) ? Wk : Wv);
        const float s = (z == 0) ? QSCALE : 1.0f;
        #pragma unroll
        for (int k = 0; k < 2; k++) {
            int f4 = tid + k * 256;            // 512 float4 = 2048 elems
            float4 v = reinterpret_cast<const float4*>(W + off)[f4];
            v.x *= s; v.y *= s; v.z *= s; v.w *= s;
            __half* dst = g_Wh + z * 32768 + off + f4 * 4;
            *reinterpret_cast<__half2*>(dst)     = __floats2half2_rn(v.x, v.y);
            *reinterpret_cast<__half2*>(dst + 2) = __floats2half2_rn(v.z, v.w);
        }
    } else {
        if (tid < 256) {
            g_bh[tid]       = __float2half(bq[tid] * QSCALE);
            g_bh[256 + tid] = __float2half(bk[tid]);
            g_bh[512 + tid] = __float2half(bv[tid]);
        }
    }
}

// ---------------------------------------------------------------------------
// Projection: pure fp16 GEMM with cp.async tiles, 2 CTAs/SM.
// Tile 128 rows x 128 cols; z-loop reuses the X tile, W double-pumped.
// ---------------------------------------------------------------------------
__global__ __launch_bounds__(256, 2) void proj_kernel()
{
    extern __shared__ __half sh[];
    __half* Xh = sh;              // [128][XP]
    __half* Wh = sh + 128 * XP;   // [128 k][XP]

    const int bn = blockIdx.x;    // 0..1
    const int bm = blockIdx.y;    // 0..127
    const int tid = threadIdx.x;

    // cp.async X tile + W(0) tile
    {
        const __half* Xg = g_Xh + (size_t)bm * 128 * EE;
        #pragma unroll
        for (int i = 0; i < 8; i++) {
            int s = tid + i * 256;
            int r = s >> 4;
            int c = s & 15;
            cpa16(su32(Xh + r * XP) + c * 16, Xg + r * EE + c * 8);
        }
        const __half* Wg = g_Wh;   // z = 0
        #pragma unroll
        for (int i = 0; i < 8; i++) {
            int s = tid + i * 256;
            int r = s >> 4;
            int c = s & 15;
            cpa16(su32(Wh + r * XP) + c * 16, Wg + r * HH + bn * 128 + c * 8);
        }
        CP_COMMIT();
    }

    const int lane = tid & 31;
    const int wid  = tid >> 5;
    const int g    = lane >> 2;
    const int tg   = lane & 3;
    const int mi   = wid & 1;
    const int nj   = wid >> 1;
    const int lr   = lane & 15;
    const int lc   = (lane >> 4) << 3;

    const unsigned aX = su32(Xh + (mi * 64 + lr) * XP + lc);
    const unsigned aW = su32(Wh + lr * XP + nj * 32 + lc);

    for (int z = 0; z < 3; z++) {
        __half* outp = (z == 0) ? g_Qh : ((z == 1) ? g_Kh : g_Vh);

        CP_WAIT0();
        __syncthreads();

        float acc[4][4][4];
        #pragma unroll
        for (int mf = 0; mf < 4; mf++)
            #pragma unroll
            for (int nf = 0; nf < 4; nf++)
                #pragma unroll
                for (int c = 0; c < 4; c++) acc[mf][nf][c] = 0.0f;

        #pragma unroll
        for (int kb = 0; kb < 8; kb++) {
            unsigned a[4][4];
            #pragma unroll
            for (int mf = 0; mf < 4; mf++)
                ldsm_x4(a[mf], aX + (mf * 16 * XP + kb * 16) * 2);
            #pragma unroll
            for (int j = 0; j < 2; j++) {
                unsigned wb[4];
                ldsm_x4t(wb, aW + (kb * 16 * XP + j * 16) * 2);
                #pragma unroll
                for (int mf = 0; mf < 4; mf++) {
                    mma16(acc[mf][2 * j],     a[mf], wb[0], wb[1]);
                    mma16(acc[mf][2 * j + 1], a[mf], wb[2], wb[3]);
                }
            }
        }
        __syncthreads();   // done reading Wh

        if (z < 2) {       // prefetch next W while we run the epilogue
            const __half* Wg = g_Wh + (z + 1) * 32768;
            #pragma unroll
            for (int i = 0; i < 8; i++) {
                int s = tid + i * 256;
                int r = s >> 4;
                int c = s & 15;
                cpa16(su32(Wh + r * XP) + c * 16, Wg + r * HH + bn * 128 + c * 8);
            }
            CP_COMMIT();
        }

        #pragma unroll
        for (int nf = 0; nf < 4; nf++) {
            const int col = nj * 32 + nf * 8 + 2 * tg;
            const float b0 = __half2float(g_bh[z * 256 + bn * 128 + col]);
            const float b1 = __half2float(g_bh[z * 256 + bn * 128 + col + 1]);
            #pragma unroll
            for (int mf = 0; mf < 4; mf++) {
                const int r0 = bm * 128 + mi * 64 + mf * 16 + g;
                __half2 h0 = __floats2half2_rn(acc[mf][nf][0] + b0, acc[mf][nf][1] + b1);
                __half2 h1 = __floats2half2_rn(acc[mf][nf][2] + b0, acc[mf][nf][3] + b1);
                *reinterpret_cast<__half2*>(&outp[(size_t)r0 * HH + bn * 128 + col])       = h0;
                *reinterpret_cast<__half2*>(&outp[(size_t)(r0 + 8) * HH + bn * 128 + col]) = h1;
            }
        }
    }
}

// ---------------------------------------------------------------------------
// Flash attention: producer/consumer mbarrier ring (no block barriers in loop).
// 288 threads: warps 0-7 = consumers (16 q rows each, BM=128), warp 8 = producer
// filling a 2-deep K/V ring (BN=64) with cp.async.
// ---------------------------------------------------------------------------
__global__ __launch_bounds__(288, 1) void flash_kernel(float* __restrict__ out)
{
    extern __shared__ __half sh[];
    const uint32_t mb_base = su32(sh);
    // mbarriers in first 64 bytes: full[0], full[1], empty[0], empty[1]
    __half* Qsm = sh + 32;                 // [128][QP]
    __half* Ks  = Qsm + 128 * QP;          // 2 x [64][QP]
    __half* Vs  = Ks + 2 * 64 * QP;        // 2 x [64][QP]

    const int b    = blockIdx.x;
    const int idx  = blockIdx.y;
    const int qt   = c_qt[idx];
    const int kind = c_kind[idx];
    const int kt_begin = (kind == 2) ? qt + 1 : 0;
    const int kt_end   = (kind == 1) ? qt : 2 * qt + 1;
    const int niter    = kt_end - kt_begin + 1;   // >= 2 always

    const int tid  = threadIdx.x;
    const int lane = tid & 31;
    const int w    = tid >> 5;             // 0..8

    if (tid == 0) {
        MBARRIER_INIT(mb_base,      1);    // full[0]  (producer arrives)
        MBARRIER_INIT(mb_base + 8,  1);    // full[1]
        MBARRIER_INIT(mb_base + 16, 8);    // empty[0] (8 consumer warps)
        MBARRIER_INIT(mb_base + 24, 8);    // empty[1]
    }

    // ---- Q tile: all 288 threads cooperate via cp.async ----
    {
        const __half* Qg = g_Qh + (size_t)(b * TT + qt * 128) * HH;
        for (int s = tid; s < 4096; s += 288) {
            int r = s >> 5;
            int c = s & 31;
            cpa16(su32(Qsm + r * QP) + c * 16, Qg + r * HH + c * 8);
        }
        CP_COMMIT();
        CP_WAIT0();
    }
    __syncthreads();   // mbarriers initialized + everyone's Q chunks visible

    if (w == 8) {
        // ================= producer =================
        auto fill = [&](int kt, int s) {
            const __half* Kg = g_Kh + (size_t)(b * TT + kt * 64) * HH;
            const __half* Vg = g_Vh + (size_t)(b * TT + kt * 64) * HH;
            __half* Kd = Ks + s * 64 * QP;
            __half* Vd = Vs + s * 64 * QP;
            #pragma unroll 8
            for (int u = 0; u < 64; u++) {
                int r = u;
                int c = lane;
                cpa16(su32(Kd + r * QP) + c * 16, Kg + r * HH + c * 8);
                cpa16(su32(Vd + r * QP) + c * 16, Vg + r * HH + c * 8);
            }
            CP_COMMIT();
        };

        fill(kt_begin, kt_begin & 1);
        for (int i = 0; i < niter; i++) {
            if (i + 1 < niter) {
                const int j = i + 1;
                const int sj = (kt_begin + j) & 1;
                if (j >= 2)
                    MBARRIER_WAIT_PARITY(mb_base + 16 + sj * 8, ((j >> 1) - 1) & 1);
                fill(kt_begin + j, sj);
                CP_WAIT1();   // fill(i) complete
            } else {
                CP_WAIT0();
            }
            if (lane == 0)
                MBARRIER_ARRIVE(mb_base + ((kt_begin + i) & 1) * 8);   // full[s]
        }
        return;   // producer done; no epilogue
    }

    // ================= consumers (warps 0..7) =================
    const int g    = lane >> 2;
    const int tg   = lane & 3;
    const int lr   = lane & 15;
    const int lc   = (lane >> 4) << 3;
    const int qrow = qt * 128 + w * 16;

    const unsigned aQ  = su32(Qsm + (w * 16 + lr) * QP + lc);
    const unsigned aK0 = su32(Ks + lr * QP + lc);
    const unsigned aV0 = su32(Vs + lr * QP + lc);
    const unsigned kvStride = 64 * QP * 2;   // bytes per ring stage

    float Oacc[32][4];
    #pragma unroll
    for (int j2 = 0; j2 < 32; j2++)
        #pragma unroll
        for (int c = 0; c < 4; c++) Oacc[j2][c] = 0.0f;
    float l0 = 0.0f, l1 = 0.0f;

    for (int i = 0; i < niter; i++) {
        const int kt = kt_begin + i;
        const int s  = kt & 1;
        MBARRIER_WAIT_PARITY(mb_base + s * 8, (i >> 1) & 1);   // full[s]

        if (kt * 64 <= qrow + 15) {   // warp has >= 1 unmasked element
            // ---- stage 1: S(16x64) = Q K^T ----
            float S[8][4];
            compute_S(S, aQ, aK0 + s * kvStride);

            // ---- softmax: P = exp2(S), masked; l per-thread ----
            const bool nm = (kt * 64 + 63 > qrow);
            const int r0 = qrow + g;
            const int r1 = qrow + 8 + g;
            unsigned Pf[4][4];
            #pragma unroll
            for (int nf = 0; nf < 8; nf++) {
                float p0 = ex2(S[nf][0]);
                float p1 = ex2(S[nf][1]);
                float p2 = ex2(S[nf][2]);
                float p3 = ex2(S[nf][3]);
                if (nm) {
                    const int col = kt * 64 + nf * 8 + 2 * tg;
                    if (col     > r0) p0 = 0.0f;
                    if (col + 1 > r0) p1 = 0.0f;
                    if (col     > r1) p2 = 0.0f;
                    if (col + 1 > r1) p3 = 0.0f;
                }
                l0 += p0 + p1;
                l1 += p2 + p3;
                const int kk = nf >> 1;
                if ((nf & 1) == 0) {
                    Pf[kk][0] = h2u(p0, p1);
                    Pf[kk][1] = h2u(p2, p3);
                } else {
                    Pf[kk][2] = h2u(p0, p1);
                    Pf[kk][3] = h2u(p2, p3);
                }
            }

            // ---- stage 2: O(16x256) += P V ----
            const unsigned aV = aV0 + s * kvStride;
            #pragma unroll
            for (int kk = 0; kk < 4; kk++) {
                #pragma unroll
                for (int j = 0; j < 16; j++) {
                    unsigned vb[4];
                    ldsm_x4t(vb, aV + (kk * 16 * QP + j * 16) * 2);
                    mma16(Oacc[2 * j],     Pf[kk], vb[0], vb[1]);
                    mma16(Oacc[2 * j + 1], Pf[kk], vb[2], vb[3]);
                }
            }
        }

        if (lane == 0)
            MBARRIER_ARRIVE(mb_base + 16 + s * 8);   // empty[s]
    }

    // ---- epilogue: reduce l across the 4 tg lanes, normalize/store ----
    l0 += __shfl_xor_sync(0xffffffffu, l0, 1);
    l0 += __shfl_xor_sync(0xffffffffu, l0, 2);
    l1 += __shfl_xor_sync(0xffffffffu, l1, 1);
    l1 += __shfl_xor_sync(0xffffffffu, l1, 2);

    if (kind == 0) {
        const float inv0 = 1.0f / l0;
        const float inv1 = 1.0f / l1;
        float* op = out + (size_t)(b * TT + qrow) * HH;
        #pragma unroll
        for (int j2 = 0; j2 < 32; j2++) {
            const int col = j2 * 8 + 2 * tg;
            float2 v0, v1;
            v0.x = Oacc[j2][0] * inv0;
            v0.y = Oacc[j2][1] * inv0;
            v1.x = Oacc[j2][2] * inv1;
            v1.y = Oacc[j2][3] * inv1;
            *reinterpret_cast<float2*>(&op[(size_t)g * HH + col])       = v0;
            *reinterpret_cast<float2*>(&op[(size_t)(g + 8) * HH + col]) = v1;
        }
    } else {
        const int half = kind - 1;
        const int ht   = b * 8 + (qt - 8);
        float* op = &g_Op[half][ht][(w * 16) * 256];
        #pragma unroll
        for (int j2 = 0; j2 < 32; j2++) {
            const int col = j2 * 8 + 2 * tg;
            float2 v0, v1;
            v0.x = Oacc[j2][0]; v0.y = Oacc[j2][1];
            v1.x = Oacc[j2][2]; v1.y = Oacc[j2][3];
            *reinterpret_cast<float2*>(&op[g * 256 + col])       = v0;
            *reinterpret_cast<float2*>(&op[(g + 8) * 256 + col]) = v1;
        }
        if (tg == 0) {
            g_lp[half][ht][w * 16 + g]     = l0;
            g_lp[half][ht][w * 16 + 8 + g] = l1;
        }
    }
}

// ---------------------------------------------------------------------------
// Combine split-KV partials: out = (o1 + o2) / (l1 + l2).
// ---------------------------------------------------------------------------
__global__ __launch_bounds__(256, 1) void combine_kernel(float* __restrict__ out)
{
    const int row  = blockIdx.x;   // 0..127
    const int tile = blockIdx.y;   // 0..63
    const int c    = threadIdx.x;  // 0..255
    const int b    = tile >> 3;
    const int qt   = 8 + (tile & 7);

    const float inv = 1.0f / (g_lp[0][tile][row] + g_lp[1][tile][row]);
    const float o1 = g_Op[0][tile][row * 256 + c];
    const float o2 = g_Op[1][tile][row * 256 + c];
    out[((size_t)(b * TT + qt * 128 + row)) * HH + c] = (o1 + o2) * inv;
}

// ---------------------------------------------------------------------------
extern "C" void kernel_launch(void* const* d_in, const int* in_sizes, int n_in,
                              void* d_out, int out_size)
{
    const float* x  = (const float*)d_in[0];
    const float* Wq = (const float*)d_in[1];
    const float* bq = (const float*)d_in[2];
    const float* Wk = (const float*)d_in[3];
    const float* bk = (const float*)d_in[4];
    const float* Wv = (const float*)d_in[5];
    const float* bv = (const float*)d_in[6];
    float* out = (float*)d_out;

    const int proj_smem  = 2 * 128 * XP * 2;                         // ~68 KB (2 CTAs/SM)
    const int flash_smem = (32 + 128 * QP + 4 * 64 * QP) * 2;        // ~198 KB

    cudaFuncSetAttribute(proj_kernel,  cudaFuncAttributeMaxDynamicSharedMemorySize, proj_smem);
    cudaFuncSetAttribute(flash_kernel, cudaFuncAttributeMaxDynamicSharedMemorySize, flash_smem);

    prep_kernel<<<1024 + 48 + 1, 256>>>(x, Wq, bq, Wk, bk, Wv, bv);
    proj_kernel<<<dim3(2, 128), 256, proj_smem>>>();
    flash_kernel<<<dim3(8, 24), 288, flash_smem>>>(out);
    combine_kernel<<<dim3(128, 64), 256>>>(out);
}

// round 16
// speedup vs baseline: 1.3187x; 1.3187x over previous
#include <cuda_runtime.h>
#include <cuda_fp16.h>
#include <math.h>
#include <stdint.h>

#define BB 8
#define TT 2048
#define EE 128
#define HH 256
#define BT (BB*TT)

#define QP  264    // halves pitch for Q/K/V smem tiles (row step = +4 banks)
#define XP  136    // halves pitch for proj tiles

// fp16 scratch
__device__ __half g_Xh[(size_t)BT*EE];     // x converted to fp16
__device__ __half g_Wh[3*EE*HH];           // W (Q-scale folded), fp16
__device__ __half g_bh[3*HH];              // biases (Q-scale folded), fp16
__device__ __half g_Qh[(size_t)BT*HH];
__device__ __half g_Kh[(size_t)BT*HH];
__device__ __half g_Vh[(size_t)BT*HH];

// split-KV partials (no-max softmax -> only O and l needed)
__device__ float g_Op[2][64][128*256];
__device__ float g_lp[2][64][128];

// LPT schedule: kind 0=light full, 1=heavy half0 (0..qt), 2=heavy half1 (qt+1..2qt+1)
__constant__ int c_qt[24]   = {15,15,7,14,14,6,13,13,12,12,5,11,11,10,10,4,9,9,8,8,3,2,1,0};
__constant__ int c_kind[24] = { 1, 2,0, 1, 2,0, 1, 2, 1, 2,0, 1, 2, 1, 2,0,1,2,1,2,0,0,0,0};

__device__ __forceinline__ unsigned su32(const void* p) {
    return (unsigned)__cvta_generic_to_shared(p);
}
__device__ __forceinline__ void ldsm_x4(unsigned* r, unsigned a) {
    asm volatile("ldmatrix.sync.aligned.m8n8.x4.shared.b16 {%0,%1,%2,%3}, [%4];"
        : "=r"(r[0]), "=r"(r[1]), "=r"(r[2]), "=r"(r[3]) : "r"(a));
}
__device__ __forceinline__ void ldsm_x4t(unsigned* r, unsigned a) {
    asm volatile("ldmatrix.sync.aligned.m8n8.x4.trans.shared.b16 {%0,%1,%2,%3}, [%4];"
        : "=r"(r[0]), "=r"(r[1]), "=r"(r[2]), "=r"(r[3]) : "r"(a));
}
__device__ __forceinline__ void mma16(float* d, const unsigned* a, unsigned b0, unsigned b1) {
    asm volatile("mma.sync.aligned.m16n8k16.row.col.f32.f16.f16.f32 "
        "{%0,%1,%2,%3},{%4,%5,%6,%7},{%8,%9},{%0,%1,%2,%3};"
        : "+f"(d[0]), "+f"(d[1]), "+f"(d[2]), "+f"(d[3])
        : "r"(a[0]), "r"(a[1]), "r"(a[2]), "r"(a[3]), "r"(b0), "r"(b1));
}
__device__ __forceinline__ void cpa16(unsigned d, const void* s) {
    asm volatile("cp.async.cg.shared.global [%0], [%1], 16;" :: "r"(d), "l"(s));
}
#define CP_COMMIT() asm volatile("cp.async.commit_group;")
#define CP_WAIT0()  asm volatile("cp.async.wait_group 0;")
#define CP_WAIT1()  asm volatile("cp.async.wait_group 1;")

__device__ __forceinline__ float ex2(float x) {
    float y; asm("ex2.approx.ftz.f32 %0, %1;" : "=f"(y) : "f"(x)); return y;
}
__device__ __forceinline__ unsigned h2u(float a, float b) {
    __half2 h = __floats2half2_rn(a, b);
    return *reinterpret_cast<unsigned*>(&h);
}

// S(16x64) = Q(16x256) K(64x256)^T for one warp. aQ/aK are per-warp ldsm bases.
__device__ __forceinline__ void compute_S(float S[8][4], unsigned aQ, unsigned aK) {
    #pragma unroll
    for (int nf = 0; nf < 8; nf++)
        #pragma unroll
        for (int c = 0; c < 4; c++) S[nf][c] = 0.0f;
    #pragma unroll
    for (int kb = 0; kb < 16; kb++) {
        unsigned qf[4];
        ldsm_x4(qf, aQ + kb * 32);
        #pragma unroll
        for (int j = 0; j < 4; j++) {
            unsigned bf[4];
            ldsm_x4(bf, aK + (j * 16 * QP + kb * 16) * 2);
            mma16(S[2 * j],     qf, bf[0], bf[2]);
            mma16(S[2 * j + 1], qf, bf[1], bf[3]);
        }
    }
}

// ---------------------------------------------------------------------------
// prep: fp32 -> fp16 conversions. Folds the softmax scale (log2e/16) into
// Wq and bq so Q comes out pre-scaled.
// grid = 1024 (x: 1024*256*2 = 524288 float4 exactly) + 48 (W) + 1 (bias).
// ---------------------------------------------------------------------------
#define QSCALE 0.0901679843431555f

__global__ __launch_bounds__(256, 4) void prep_kernel(
    const float* __restrict__ x,
    const float* __restrict__ Wq, const float* __restrict__ bq,
    const float* __restrict__ Wk, const float* __restrict__ bk,
    const float* __restrict__ Wv, const float* __restrict__ bv)
{
    const int bx = blockIdx.x;
    const int tid = threadIdx.x;
    if (bx < 1024) {
        // x: 2,097,152 floats = 524,288 float4; 1024 blocks x 256 thr x 2
        const float4* xs = reinterpret_cast<const float4*>(x);
        #pragma unroll
        for (int k = 0; k < 2; k++) {
            size_t f = (size_t)bx * 256 + tid + (size_t)k * 262144;
            float4 v = xs[f];
            reinterpret_cast<__half2*>(g_Xh)[2 * f]     = __floats2half2_rn(v.x, v.y);
            reinterpret_cast<__half2*>(g_Xh)[2 * f + 1] = __floats2half2_rn(v.z, v.w);
        }
    } else if (bx < 1024 + 48) {
        const int wb = bx - 1024;
        const int z = wb >> 4;                 // 0..2
        const int off = (wb & 15) * 2048;      // element offset within W (32768)
        const float* W = (z == 0) ? Wq : ((z == 1) ? Wk : Wv);
        const float s = (z == 0) ? QSCALE : 1.0f;
        #pragma unroll
        for (int k = 0; k < 2; k++) {
            int f4 = tid + k * 256;            // 512 float4 = 2048 elems
            float4 v = reinterpret_cast<const float4*>(W + off)[f4];
            v.x *= s; v.y *= s; v.z *= s; v.w *= s;
            __half* dst = g_Wh + z * 32768 + off + f4 * 4;
            *reinterpret_cast<__half2*>(dst)     = __floats2half2_rn(v.x, v.y);
            *reinterpret_cast<__half2*>(dst + 2) = __floats2half2_rn(v.z, v.w);
        }
    } else {
        if (tid < 256) {
            g_bh[tid]       = __float2half(bq[tid] * QSCALE);
            g_bh[256 + tid] = __float2half(bk[tid]);
            g_bh[512 + tid] = __float2half(bv[tid]);
        }
    }
}

// ---------------------------------------------------------------------------
// Projection: pure fp16 GEMM with cp.async tiles, 2 CTAs/SM.
// Tile 128 rows x 128 cols; z-loop reuses the X tile, W double-pumped.
// ---------------------------------------------------------------------------
__global__ __launch_bounds__(256, 2) void proj_kernel()
{
    extern __shared__ __half sh[];
    __half* Xh = sh;              // [128][XP]
    __half* Wh = sh + 128 * XP;   // [128 k][XP]

    const int bn = blockIdx.x;    // 0..1
    const int bm = blockIdx.y;    // 0..127
    const int tid = threadIdx.x;

    // cp.async X tile + W(0) tile
    {
        const __half* Xg = g_Xh + (size_t)bm * 128 * EE;
        #pragma unroll
        for (int i = 0; i < 8; i++) {
            int s = tid + i * 256;
            int r = s >> 4;
            int c = s & 15;
            cpa16(su32(Xh + r * XP) + c * 16, Xg + r * EE + c * 8);
        }
        const __half* Wg = g_Wh;   // z = 0
        #pragma unroll
        for (int i = 0; i < 8; i++) {
            int s = tid + i * 256;
            int r = s >> 4;
            int c = s & 15;
            cpa16(su32(Wh + r * XP) + c * 16, Wg + r * HH + bn * 128 + c * 8);
        }
        CP_COMMIT();
    }

    const int lane = tid & 31;
    const int wid  = tid >> 5;
    const int g    = lane >> 2;
    const int tg   = lane & 3;
    const int mi   = wid & 1;
    const int nj   = wid >> 1;
    const int lr   = lane & 15;
    const int lc   = (lane >> 4) << 3;

    const unsigned aX = su32(Xh + (mi * 64 + lr) * XP + lc);
    const unsigned aW = su32(Wh + lr * XP + nj * 32 + lc);

    for (int z = 0; z < 3; z++) {
        __half* outp = (z == 0) ? g_Qh : ((z == 1) ? g_Kh : g_Vh);

        CP_WAIT0();
        __syncthreads();

        float acc[4][4][4];
        #pragma unroll
        for (int mf = 0; mf < 4; mf++)
            #pragma unroll
            for (int nf = 0; nf < 4; nf++)
                #pragma unroll
                for (int c = 0; c < 4; c++) acc[mf][nf][c] = 0.0f;

        #pragma unroll
        for (int kb = 0; kb < 8; kb++) {
            unsigned a[4][4];
            #pragma unroll
            for (int mf = 0; mf < 4; mf++)
                ldsm_x4(a[mf], aX + (mf * 16 * XP + kb * 16) * 2);
            #pragma unroll
            for (int j = 0; j < 2; j++) {
                unsigned wb[4];
                ldsm_x4t(wb, aW + (kb * 16 * XP + j * 16) * 2);
                #pragma unroll
                for (int mf = 0; mf < 4; mf++) {
                    mma16(acc[mf][2 * j],     a[mf], wb[0], wb[1]);
                    mma16(acc[mf][2 * j + 1], a[mf], wb[2], wb[3]);
                }
            }
        }
        __syncthreads();   // done reading Wh

        if (z < 2) {       // prefetch next W while we run the epilogue
            const __half* Wg = g_Wh + (z + 1) * 32768;
            #pragma unroll
            for (int i = 0; i < 8; i++) {
                int s = tid + i * 256;
                int r = s >> 4;
                int c = s & 15;
                cpa16(su32(Wh + r * XP) + c * 16, Wg + r * HH + bn * 128 + c * 8);
            }
            CP_COMMIT();
        }

        #pragma unroll
        for (int nf = 0; nf < 4; nf++) {
            const int col = nj * 32 + nf * 8 + 2 * tg;
            const float b0 = __half2float(g_bh[z * 256 + bn * 128 + col]);
            const float b1 = __half2float(g_bh[z * 256 + bn * 128 + col + 1]);
            #pragma unroll
            for (int mf = 0; mf < 4; mf++) {
                const int r0 = bm * 128 + mi * 64 + mf * 16 + g;
                __half2 h0 = __floats2half2_rn(acc[mf][nf][0] + b0, acc[mf][nf][1] + b1);
                __half2 h1 = __floats2half2_rn(acc[mf][nf][2] + b0, acc[mf][nf][3] + b1);
                *reinterpret_cast<__half2*>(&outp[(size_t)r0 * HH + bn * 128 + col])       = h0;
                *reinterpret_cast<__half2*>(&outp[(size_t)(r0 + 8) * HH + bn * 128 + col]) = h1;
            }
        }
    }
}

// ---------------------------------------------------------------------------
// Flash attention (R11 structure): FA2 + split-KV + no-max softmax +
// cross-tile S pipelining. 8 warps x 16 query rows (BM=128), 256 threads.
// ---------------------------------------------------------------------------
__global__ __launch_bounds__(256, 1) void flash_kernel(float* __restrict__ out)
{
    extern __shared__ __half sh[];
    __half* Qsm = sh;                     // [128][QP]
    __half* Ks  = sh + 128 * QP;          // 2 x [64][QP]
    __half* Vs  = Ks + 2 * 64 * QP;       // 2 x [64][QP]

    const int b    = blockIdx.x;
    const int idx  = blockIdx.y;
    const int qt   = c_qt[idx];
    const int kind = c_kind[idx];
    const int kt_begin = (kind == 2) ? qt + 1 : 0;
    const int kt_end   = (kind == 1) ? qt : 2 * qt + 1;   // every range has >= 2 tiles

    const int tid  = threadIdx.x;
    const int lane = tid & 31;
    const int w    = tid >> 5;
    const int g    = lane >> 2;
    const int tg   = lane & 3;
    const int lr   = lane & 15;
    const int lc   = (lane >> 4) << 3;

    const int qrow = qt * 128 + w * 16;

    // ---- prologue: group0 = Q + KV(kt_begin), group1 = KV(kt_begin+1) ----
    {
        const __half* Qg = g_Qh + (size_t)(b * TT + qt * 128) * HH;
        const __half* Kg = g_Kh + (size_t)(b * TT + kt_begin * 64) * HH;
        const __half* Vg = g_Vh + (size_t)(b * TT + kt_begin * 64) * HH;
        __half* Kd = Ks + (kt_begin & 1) * 64 * QP;
        __half* Vd = Vs + (kt_begin & 1) * 64 * QP;
        #pragma unroll
        for (int i = 0; i < 16; i++) {
            int s = tid + i * 256;
            int r = s >> 5;
            int c8 = (s & 31) * 8;
            cpa16(su32(Qsm + r * QP + c8), Qg + r * HH + c8);
        }
        #pragma unroll
        for (int i = 0; i < 8; i++) {
            int s = tid + i * 256;
            int r = s >> 5;
            int c8 = (s & 31) * 8;
            cpa16(su32(Kd + r * QP + c8), Kg + r * HH + c8);
            cpa16(su32(Vd + r * QP + c8), Vg + r * HH + c8);
        }
        CP_COMMIT();

        const int k1 = kt_begin + 1;
        const __half* Kg1 = g_Kh + (size_t)(b * TT + k1 * 64) * HH;
        const __half* Vg1 = g_Vh + (size_t)(b * TT + k1 * 64) * HH;
        __half* Kd1 = Ks + (k1 & 1) * 64 * QP;
        __half* Vd1 = Vs + (k1 & 1) * 64 * QP;
        #pragma unroll
        for (int i = 0; i < 8; i++) {
            int s = tid + i * 256;
            int r = s >> 5;
            int c8 = (s & 31) * 8;
            cpa16(su32(Kd1 + r * QP + c8), Kg1 + r * HH + c8);
            cpa16(su32(Vd1 + r * QP + c8), Vg1 + r * HH + c8);
        }
        CP_COMMIT();
    }
    CP_WAIT1();         // Q + KV(kt_begin) resident; KV(kt_begin+1) in flight
    __syncthreads();

    const unsigned aQ  = su32(Qsm + (w * 16 + lr) * QP + lc);
    const unsigned aK0 = su32(Ks + lr * QP + lc);
    const unsigned aK1 = aK0 + 64 * QP * 2;
    const unsigned aV0 = su32(Vs + lr * QP + lc);
    const unsigned aV1 = aV0 + 64 * QP * 2;

    float S[8][4];
    compute_S(S, aQ, (kt_begin & 1) ? aK1 : aK0);   // kt_begin active for every warp

    float Oacc[32][4];
    #pragma unroll
    for (int j2 = 0; j2 < 32; j2++)
        #pragma unroll
        for (int c = 0; c < 4; c++) Oacc[j2][c] = 0.0f;
    float l0 = 0.0f, l1 = 0.0f;

    for (int kt = kt_begin; kt <= kt_end; ++kt) {
        const bool act = (kt * 64 <= qrow + 15);

        // ---- softmax: P = exp2(S), masked; l accumulates per-thread ----
        unsigned Pf[4][4];
        if (act) {
            const bool nm = (kt * 64 + 63 > qrow);
            const int r0 = qrow + g;
            const int r1 = qrow + 8 + g;
            #pragma unroll
            for (int nf = 0; nf < 8; nf++) {
                float p0 = ex2(S[nf][0]);
                float p1 = ex2(S[nf][1]);
                float p2 = ex2(S[nf][2]);
                float p3 = ex2(S[nf][3]);
                if (nm) {
                    const int col = kt * 64 + nf * 8 + 2 * tg;
                    if (col     > r0) p0 = 0.0f;
                    if (col + 1 > r0) p1 = 0.0f;
                    if (col     > r1) p2 = 0.0f;
                    if (col + 1 > r1) p3 = 0.0f;
                }
                l0 += p0 + p1;
                l1 += p2 + p3;
                const int kk = nf >> 1;
                if ((nf & 1) == 0) {
                    Pf[kk][0] = h2u(p0, p1);
                    Pf[kk][1] = h2u(p2, p3);
                } else {
                    Pf[kk][2] = h2u(p0, p1);
                    Pf[kk][3] = h2u(p2, p3);
                }
            }
        }

        const bool have_next = (kt < kt_end);
        if (have_next) {
            CP_WAIT0();          // KV(kt+1) resident
            __syncthreads();
            if ((kt + 1) * 64 <= qrow + 15)
                compute_S(S, aQ, ((kt + 1) & 1) ? aK1 : aK0);   // next tile's S
        }

        // ---- stage2: O += P V(kt) (independent of compute_S above) ----
        if (act) {
            const unsigned aV = (kt & 1) ? aV1 : aV0;
            #pragma unroll
            for (int kk = 0; kk < 4; kk++) {
                #pragma unroll
                for (int j = 0; j < 16; j++) {
                    unsigned vb[4];
                    ldsm_x4t(vb, aV + (kk * 16 * QP + j * 16) * 2);
                    mma16(Oacc[2 * j],     Pf[kk], vb[0], vb[1]);
                    mma16(Oacc[2 * j + 1], Pf[kk], vb[2], vb[3]);
                }
            }
        }

        // ---- prefetch KV(kt+2) into buffer (kt&1) after all reads done ----
        if (kt + 2 <= kt_end) {
            __syncthreads();
            const __half* Kg = g_Kh + (size_t)(b * TT + (kt + 2) * 64) * HH;
            const __half* Vg = g_Vh + (size_t)(b * TT + (kt + 2) * 64) * HH;
            __half* Kd = Ks + (kt & 1) * 64 * QP;
            __half* Vd = Vs + (kt & 1) * 64 * QP;
            #pragma unroll
            for (int i = 0; i < 8; i++) {
                int s = tid + i * 256;
                int r = s >> 5;
                int c8 = (s & 31) * 8;
                cpa16(su32(Kd + r * QP + c8), Kg + r * HH + c8);
                cpa16(su32(Vd + r * QP + c8), Vg + r * HH + c8);
            }
            CP_COMMIT();
        }
    }

    // ---- epilogue: reduce l across the 4 tg lanes, normalize/store ----
    l0 += __shfl_xor_sync(0xffffffffu, l0, 1);
    l0 += __shfl_xor_sync(0xffffffffu, l0, 2);
    l1 += __shfl_xor_sync(0xffffffffu, l1, 1);
    l1 += __shfl_xor_sync(0xffffffffu, l1, 2);

    if (kind == 0) {
        const float inv0 = 1.0f / l0;
        const float inv1 = 1.0f / l1;
        float* op = out + (size_t)(b * TT + qrow) * HH;
        #pragma unroll
        for (int j2 = 0; j2 < 32; j2++) {
            const int col = j2 * 8 + 2 * tg;
            float2 v0, v1;
            v0.x = Oacc[j2][0] * inv0;
            v0.y = Oacc[j2][1] * inv0;
            v1.x = Oacc[j2][2] * inv1;
            v1.y = Oacc[j2][3] * inv1;
            *reinterpret_cast<float2*>(&op[(size_t)g * HH + col])       = v0;
            *reinterpret_cast<float2*>(&op[(size_t)(g + 8) * HH + col]) = v1;
        }
    } else {
        const int half = kind - 1;
        const int ht   = b * 8 + (qt - 8);
        float* op = &g_Op[half][ht][(w * 16) * 256];
        #pragma unroll
        for (int j2 = 0; j2 < 32; j2++) {
            const int col = j2 * 8 + 2 * tg;
            float2 v0, v1;
            v0.x = Oacc[j2][0]; v0.y = Oacc[j2][1];
            v1.x = Oacc[j2][2]; v1.y = Oacc[j2][3];
            *reinterpret_cast<float2*>(&op[g * 256 + col])       = v0;
            *reinterpret_cast<float2*>(&op[(g + 8) * 256 + col]) = v1;
        }
        if (tg == 0) {
            g_lp[half][ht][w * 16 + g]     = l0;
            g_lp[half][ht][w * 16 + 8 + g] = l1;
        }
    }
}

// ---------------------------------------------------------------------------
// Combine split-KV partials: out = (o1 + o2) / (l1 + l2). float4 vectorized.
// grid (4, 64): block handles 32 rows x 64 float4-cols of one heavy tile.
// ---------------------------------------------------------------------------
__global__ __launch_bounds__(256, 4) void combine_kernel(float* __restrict__ out)
{
    const int rb   = blockIdx.x;   // 0..3 (row group of 32)
    const int tile = blockIdx.y;   // 0..63
    const int tid  = threadIdx.x;
    const int b    = tile >> 3;
    const int qt   = 8 + (tile & 7);

    const float4* o1p = reinterpret_cast<const float4*>(&g_Op[0][tile][0]);
    const float4* o2p = reinterpret_cast<const float4*>(&g_Op[1][tile][0]);

    #pragma unroll
    for (int i = 0; i < 8; i++) {
        const int s   = tid + i * 256;         // 0..2047
        const int row = rb * 32 + (s >> 6);    // 32 rows per block
        const int c4  = s & 63;                // 64 float4 per row
        const float inv = 1.0f / (g_lp[0][tile][row] + g_lp[1][tile][row]);
        const float4 o1 = o1p[row * 64 + c4];
        const float4 o2 = o2p[row * 64 + c4];
        float4 v;
        v.x = (o1.x + o2.x) * inv;
        v.y = (o1.y + o2.y) * inv;
        v.z = (o1.z + o2.z) * inv;
        v.w = (o1.w + o2.w) * inv;
        reinterpret_cast<float4*>(
            out + ((size_t)(b * TT + qt * 128 + row)) * HH)[c4] = v;
    }
}

// ---------------------------------------------------------------------------
extern "C" void kernel_launch(void* const* d_in, const int* in_sizes, int n_in,
                              void* d_out, int out_size)
{
    const float* x  = (const float*)d_in[0];
    const float* Wq = (const float*)d_in[1];
    const float* bq = (const float*)d_in[2];
    const float* Wk = (const float*)d_in[3];
    const float* bk = (const float*)d_in[4];
    const float* Wv = (const float*)d_in[5];
    const float* bv = (const float*)d_in[6];
    float* out = (float*)d_out;

    const int proj_smem  = 2 * 128 * XP * 2;                    // ~68 KB (2 CTAs/SM)
    const int flash_smem = (128 * QP + 4 * 64 * QP) * 2;        // ~198 KB

    cudaFuncSetAttribute(proj_kernel,  cudaFuncAttributeMaxDynamicSharedMemorySize, proj_smem);
    cudaFuncSetAttribute(flash_kernel, cudaFuncAttributeMaxDynamicSharedMemorySize, flash_smem);

    prep_kernel<<<1024 + 48 + 1, 256>>>(x, Wq, bq, Wk, bk, Wv, bv);
    proj_kernel<<<dim3(2, 128), 256, proj_smem>>>();
    flash_kernel<<<dim3(8, 24), 256, flash_smem>>>(out);
    combine_kernel<<<dim3(4, 64), 256>>>(out);
}